// round 10
// baseline (speedup 1.0000x reference)
#include <cuda_runtime.h>
#include <cuda_bf16.h>

#define TT 512
#define BB 32
#define VV 8000
#define LL 100
#define SS (2*LL+1)   // 201
#define NEGF (-1e30f)
#define LOG2E 1.4426950408889634f
#define LN2   0.6931471805599453f

#define SWARPS 9      // scan warps per sample
#define OWN   24      // owned states per warp (lanes 8..31)
#define MIR    8      // mirror lanes (0..7) = prev warp's top 8 states
#define NPAIRS 255    // 2-step pairs: pair p covers t = 2p+1, 2p+2 (t up to 510)
#define NGRP  127     // groups of 2 pairs (4 t-steps) per barrier; leftover pair 254

// Scratch (allocation-free rule: __device__ globals)
__device__ float g_lp[TT*BB*SS];          // log2-domain emissions (even t rows + 511)
__device__ float g_w[NPAIRS*BB*5*SS];     // 2-step transition weights, 32.8 MB

__device__ __forceinline__ float ex2f(float x) {
    float r; asm("ex2.approx.ftz.f32 %0, %1;" : "=f"(r) : "f"(x)); return r;
}
__device__ __forceinline__ float lg2f(float x) {
    float r; asm("lg2.approx.ftz.f32 %0, %1;" : "=f"(r) : "f"(x)); return r;
}
__device__ __forceinline__ float lse2w(float x, float y) {       // log2 domain
    float m = fmaxf(x, y);
    return m + lg2f(ex2f(x - m) + ex2f(y - m));
}
__device__ __forceinline__ float lse3w(float x, float y, float z) {
    float m = fmaxf(x, fmaxf(y, z));
    return m + lg2f(ex2f(x - m) + ex2f(y - m) + ex2f(z - m));
}

// ---------------------------------------------------------------------------
// K1: logZ over V, gather lp_ext (log2 domain), and for odd t<=509 compute the
//     2-step composed transition weights w0..w4 for pair p=(t-1)/2.
// ---------------------------------------------------------------------------
__global__ __launch_bounds__(256) void logz_gather_kernel(const float* __restrict__ acts,
                                                          const int* __restrict__ targets,
                                                          float* __restrict__ out) {
    const int row = blockIdx.x;                    // t*BB + b
    const int t   = row / BB;
    const int b   = row % BB;
    const float* __restrict__ rowp = acts + (size_t)row * VV;
    const float4* __restrict__ p = (const float4*)rowp;
    const int tid = threadIdx.x;

    if (row == 0 && tid == 0) out[0] = 0.f;        // zero the batch-mean accumulator

    float m = NEGF, s = 0.f;
    #pragma unroll 4
    for (int i = tid; i < VV/4; i += 256) {
        float4 v = p[i];
        float mx = fmaxf(fmaxf(v.x, v.y), fmaxf(v.z, v.w));
        if (mx > m) { s *= __expf(m - mx); m = mx; }
        s += __expf(v.x - m) + __expf(v.y - m) + __expf(v.z - m) + __expf(v.w - m);
    }
    #pragma unroll
    for (int off = 16; off; off >>= 1) {
        float m2 = __shfl_xor_sync(0xffffffffu, m, off);
        float s2 = __shfl_xor_sync(0xffffffffu, s, off);
        float M = fmaxf(m, m2);
        s = s * __expf(m - M) + s2 * __expf(m2 - M);
        m = M;
    }
    __shared__ float sm[8], sv[8];
    __shared__ float sLogZ;
    __shared__ float slp[SS];
    __shared__ unsigned char scs[SS];
    int w = tid >> 5;
    if ((tid & 31) == 0) { sm[w] = m; sv[w] = s; }
    __syncthreads();
    if (tid == 0) {
        float M = sm[0], Sv = sv[0];
        #pragma unroll
        for (int i = 1; i < 8; i++) {
            float m2 = sm[i], s2 = sv[i];
            float Mn = fmaxf(M, m2);
            Sv = Sv * __expf(M - Mn) + s2 * __expf(m2 - Mn);
            M = Mn;
        }
        sLogZ = M + __logf(Sv);
    }
    __syncthreads();

    // Gather 201 extended-label emissions (L1 hits), log2 domain; stage in smem.
    if (tid < SS) {
        int lab = (tid & 1) ? __ldg(&targets[b*LL + (tid >> 1)]) : 0;
        float lp2 = (rowp[lab] - sLogZ) * LOG2E;
        slp[tid] = lp2;
        bool csf = false;
        if (tid & 1) {
            int pl = (tid >= 3) ? __ldg(&targets[b*LL + ((tid - 2) >> 1)]) : -1;
            csf = (lab != 0) && (lab != pl);
        }
        scs[tid] = csf ? 1 : 0;
        // scan only reads even rows + row 511 directly
        if (((t & 1) == 0) || t == TT-1)
            g_lp[(size_t)row * SS + tid] = lp2;
    }
    __syncthreads();

    // 2-step weights for odd t (pair p = (t-1)/2, covering t, t+1)
    if ((t & 1) && t <= TT-3 && tid < SS) {
        int sidx = tid;
        float L0 = slp[sidx];
        float L1 = (sidx >= 1) ? slp[sidx-1] : NEGF;
        float L2 = (sidx >= 2) ? slp[sidx-2] : NEGF;
        bool c0 = scs[sidx];
        bool c1 = (sidx >= 1) ? (scs[sidx-1] != 0) : false;
        bool c2 = (sidx >= 2) ? (scs[sidx-2] != 0) : false;
        float w0 = L0;
        float w1 = lse2w(L0, L1);
        float w2 = lse3w(c0 ? L0 : NEGF, L1, c0 ? L2 : NEGF);
        float w3 = lse2w(c1 ? L1 : NEGF, c0 ? L2 : NEGF);
        float w4 = (c0 && c2) ? L2 : NEGF;
        int pr = (t - 1) >> 1;
        size_t base = ((size_t)(pr*BB + b) * 5) * SS + sidx;
        g_w[base + 0*SS] = w0;
        g_w[base + 1*SS] = w1;
        g_w[base + 2*SS] = w2;
        g_w[base + 3*SS] = w3;
        g_w[base + 4*SS] = w4;
    }
}

// ---------------------------------------------------------------------------
// K2: alpha scan via composed 2-step operator. One 5-term lse per 2 steps;
//     2 pairs (4 t-steps) per barrier (MIR=8, erosion 4/pair).
// ---------------------------------------------------------------------------
__global__ __launch_bounds__(32*SWARPS) void scan_kernel(const int* __restrict__ targets,
                                                         const int* __restrict__ act_lens,
                                                         const int* __restrict__ label_lens,
                                                         float* __restrict__ out) {
    const int b   = blockIdx.x;
    const int tid = threadIdx.x;
    const int w   = tid >> 5;
    const int l   = tid & 31;
    const int s   = OWN * w + l - MIR;         // state id (mirrors for l<8)
    const bool live = (s >= 0 && s < SS);
    const bool owned = (l >= MIR) && live;
    const int alen = act_lens[b];

    __shared__ float bnd[2][SWARPS*MIR];
    __shared__ float fin[SS];

    bool cs = false;                           // can_skip (odd states only)
    if (live && (s & 1)) {
        int cl = targets[b*LL + (s >> 1)];
        int pl = (s >= 3) ? targets[b*LL + ((s - 2) >> 1)] : -1;
        cs = (cl != 0) && (cl != pl);
    }

    // composed 2-step operator
    auto pairstep = [&](float av, float w0, float w1, float w2, float w3,
                        float w4, float lpn) -> float {
        float x0 = av + w0;
        float x1 = __shfl_up_sync(0xffffffffu, av, 1) + w1;
        float x2 = __shfl_up_sync(0xffffffffu, av, 2) + w2;
        float x3 = __shfl_up_sync(0xffffffffu, av, 3) + w3;
        float x4 = __shfl_up_sync(0xffffffffu, av, 4) + w4;
        float mm = fmaxf(fmaxf(fmaxf(x0, x1), fmaxf(x2, x3)), x4);
        float r = ex2f(x0 - mm) + ex2f(x1 - mm) + ex2f(x2 - mm)
                + ex2f(x3 - mm) + ex2f(x4 - mm);
        float nv = mm + lg2f(r) + lpn;
        return live ? nv : NEGF;
    };
    // classic single step (lse3)
    auto step1 = [&](float av, float lp, int t) -> float {
        float x2 = __shfl_up_sync(0xffffffffu, av, 1);
        float x3 = __shfl_up_sync(0xffffffffu, av, 2);
        float x3e = cs ? x3 : NEGF;
        float mm = fmaxf(av, fmaxf(x2, x3e));
        float r = ex2f(av - mm) + ex2f(x2 - mm) + ex2f(x3e - mm);
        float nv = mm + lg2f(r) + lp;
        nv = (t < alen) ? nv : av;
        return live ? nv : NEGF;
    };

    // alpha[0]
    float a = NEGF;
    if (live && s <= 1) a = g_lp[(size_t)b * SS + s];

    if (alen >= TT) {
        // ---------------- fast path: no freezing anywhere ----------------
        // tail prefetch: leftover pair p=254 (t=509,510) + final step t=511
        float wT0, wT1, wT2, wT3, wT4, lnT, lnTail;
        {
            size_t base = ((size_t)(254*BB + b) * 5) * SS + (live ? s : 0);
            wT0 = live ? g_w[base + 0*SS] : NEGF;
            wT1 = live ? g_w[base + 1*SS] : NEGF;
            wT2 = live ? g_w[base + 2*SS] : NEGF;
            wT3 = live ? g_w[base + 3*SS] : NEGF;
            wT4 = live ? g_w[base + 4*SS] : NEGF;
            lnT    = live ? g_lp[(size_t)(510*BB + b)*SS + s] : 0.f;
            lnTail = live ? g_lp[(size_t)(511*BB + b)*SS + s] : 0.f;
        }

        float wA[10], wB[10], lnA0, lnA1, lnB0, lnB1;
        #pragma unroll
        for (int i = 0; i < 5; i++) {
            wA[i]   = live ? g_w[((size_t)(0*BB + b)*5 + i)*SS + s] : NEGF;
            wA[5+i] = live ? g_w[((size_t)(1*BB + b)*5 + i)*SS + s] : NEGF;
        }
        lnA0 = live ? g_lp[(size_t)(2*BB + b)*SS + s] : 0.f;
        lnA1 = live ? g_lp[(size_t)(4*BB + b)*SS + s] : 0.f;

        for (int g = 0; g < NGRP; g++) {
            int gp = g + 1;
            bool ok = live && (gp < NGRP);
            #pragma unroll
            for (int i = 0; i < 5; i++) {
                wB[i]   = ok ? g_w[((size_t)((2*gp)*BB + b)*5 + i)*SS + s]   : NEGF;
                wB[5+i] = ok ? g_w[((size_t)((2*gp+1)*BB + b)*5 + i)*SS + s] : NEGF;
            }
            lnB0 = ok ? g_lp[(size_t)((4*gp+2)*BB + b)*SS + s] : 0.f;
            lnB1 = ok ? g_lp[(size_t)((4*gp+4)*BB + b)*SS + s] : 0.f;

            // pair A (t = 4g+1,4g+2), pair B (t = 4g+3,4g+4)
            a = pairstep(a, wA[0], wA[1], wA[2], wA[3], wA[4], lnA0);
            a = pairstep(a, wA[5], wA[6], wA[7], wA[8], wA[9], lnA1);

            // boundary exchange (mirrors fully consumed: 2 pairs x reach-4)
            if (l >= 32 - MIR) bnd[g & 1][w*MIR + (l - (32 - MIR))] = a;
            __syncthreads();
            if (l < MIR) a = (w > 0) ? bnd[g & 1][(w - 1)*MIR + l] : NEGF;

            #pragma unroll
            for (int i = 0; i < 10; i++) wA[i] = wB[i];
            lnA0 = lnB0; lnA1 = lnB1;
        }

        // leftover pair p=254 (t=509,510): consumes mirror lanes 0..3
        a = pairstep(a, wT0, wT1, wT2, wT3, wT4, lnT);
        // final step t=511: consumes 2 more mirror lanes (4..5 still valid)
        a = step1(a, lnTail, 511);
    } else {
        // ---------------- fallback: generic per-step smem scan ----------------
        __shared__ float sal[2][SS];
        if (live) sal[0][s] = a;
        __syncthreads();
        int cur = 1;
        for (int t = 1; t < TT; t++) {
            if (live) {
                float a1 = sal[cur^1][s];
                float a2 = (s >= 1) ? sal[cur^1][s-1] : NEGF;
                float a3 = (cs && s >= 2) ? sal[cur^1][s-2] : NEGF;
                float mm = fmaxf(a1, fmaxf(a2, a3));
                float r = ex2f(a1 - mm) + ex2f(a2 - mm) + ex2f(a3 - mm);
                float lp = ((t & 1) == 0 || t == TT-1)
                         ? g_lp[(size_t)(t*BB + b)*SS + s]
                         : (t < TT-2 ? (g_w[((size_t)(((t-1)>>1)*BB + b)*5 + 0)*SS + s]) : 0.f);
                float nv = mm + lg2f(r) + lp;   // w0 == lp for odd t rows
                sal[cur][s] = (t < alen) ? nv : a1;
            }
            __syncthreads();
            cur ^= 1;
        }
        a = live ? sal[cur^1][s] : NEGF;
    }

    if (owned) fin[s] = a;
    __syncthreads();
    if (tid == 0) {
        int sl = 2 * label_lens[b];
        float x = fin[sl], y = fin[sl - 1];
        float m = fmaxf(x, y);
        float ll2 = m + lg2f(ex2f(x - m) + ex2f(y - m));   // log2 domain
        atomicAdd(out, -ll2 * (LN2 / (float)BB));
    }
}

// ---------------------------------------------------------------------------
extern "C" void kernel_launch(void* const* d_in, const int* in_sizes, int n_in,
                              void* d_out, int out_size) {
    const float* acts       = (const float*)d_in[0];
    const int*   targets    = (const int*)d_in[1];
    const int*   act_lens   = (const int*)d_in[2];
    const int*   label_lens = (const int*)d_in[3];
    float* out = (float*)d_out;

    logz_gather_kernel<<<TT*BB, 256>>>(acts, targets, out);
    scan_kernel<<<BB, 32*SWARPS>>>(targets, act_lens, label_lens, out);
}

// round 11
// speedup vs baseline: 1.1788x; 1.1788x over previous
#include <cuda_runtime.h>
#include <cuda_bf16.h>

#define TT 512
#define BB 32
#define VV 8000
#define LL 100
#define SS (2*LL+1)   // 201
#define NEGF (-1e30f)
#define LOG2E 1.4426950408889634f
#define LN2   0.6931471805599453f

#define SWARPS 9      // scan warps per sample
#define OWN   24      // owned states per warp (lanes 8..31)
#define MIR    8      // mirror lanes (0..7) = prev warp's top 8 states
#define NPAIRS 255    // 2-step pairs: pair p covers t = 2p+1, 2p+2 (t up to 510)
#define NGRP  127     // groups of 2 pairs (4 t-steps); leftover pair 254 + step 511

// Scratch (allocation-free rule: __device__ globals)
__device__ float g_lp[TT*BB*SS];          // log2-domain emissions (even t rows + 511)
__device__ float g_w[NPAIRS*BB*5*SS];     // 2-step transition weights, 32.8 MB

__device__ __forceinline__ float ex2f(float x) {
    float r; asm("ex2.approx.ftz.f32 %0, %1;" : "=f"(r) : "f"(x)); return r;
}
__device__ __forceinline__ float lg2f(float x) {
    float r; asm("lg2.approx.ftz.f32 %0, %1;" : "=f"(r) : "f"(x)); return r;
}
__device__ __forceinline__ float lse2w(float x, float y) {       // log2 domain
    float m = fmaxf(x, y);
    return m + lg2f(ex2f(x - m) + ex2f(y - m));
}
__device__ __forceinline__ float lse3w(float x, float y, float z) {
    float m = fmaxf(x, fmaxf(y, z));
    return m + lg2f(ex2f(x - m) + ex2f(y - m) + ex2f(z - m));
}

// ---------------------------------------------------------------------------
// K1: logZ over V, gather lp_ext (log2 domain), and for odd t<=509 compute the
//     2-step composed transition weights w0..w4 for pair p=(t-1)/2.
// ---------------------------------------------------------------------------
__global__ __launch_bounds__(256) void logz_gather_kernel(const float* __restrict__ acts,
                                                          const int* __restrict__ targets,
                                                          float* __restrict__ out) {
    const int row = blockIdx.x;                    // t*BB + b
    const int t   = row / BB;
    const int b   = row % BB;
    const float* __restrict__ rowp = acts + (size_t)row * VV;
    const float4* __restrict__ p = (const float4*)rowp;
    const int tid = threadIdx.x;

    if (row == 0 && tid == 0) out[0] = 0.f;        // zero the batch-mean accumulator

    float m = NEGF, s = 0.f;
    #pragma unroll 4
    for (int i = tid; i < VV/4; i += 256) {
        float4 v = p[i];
        float mx = fmaxf(fmaxf(v.x, v.y), fmaxf(v.z, v.w));
        if (mx > m) { s *= __expf(m - mx); m = mx; }
        s += __expf(v.x - m) + __expf(v.y - m) + __expf(v.z - m) + __expf(v.w - m);
    }
    #pragma unroll
    for (int off = 16; off; off >>= 1) {
        float m2 = __shfl_xor_sync(0xffffffffu, m, off);
        float s2 = __shfl_xor_sync(0xffffffffu, s, off);
        float M = fmaxf(m, m2);
        s = s * __expf(m - M) + s2 * __expf(m2 - M);
        m = M;
    }
    __shared__ float sm[8], sv[8];
    __shared__ float sLogZ;
    __shared__ float slp[SS];
    __shared__ unsigned char scs[SS];
    int w = tid >> 5;
    if ((tid & 31) == 0) { sm[w] = m; sv[w] = s; }
    __syncthreads();
    if (tid == 0) {
        float M = sm[0], Sv = sv[0];
        #pragma unroll
        for (int i = 1; i < 8; i++) {
            float m2 = sm[i], s2 = sv[i];
            float Mn = fmaxf(M, m2);
            Sv = Sv * __expf(M - Mn) + s2 * __expf(m2 - Mn);
            M = Mn;
        }
        sLogZ = M + __logf(Sv);
    }
    __syncthreads();

    // Gather 201 extended-label emissions (L1 hits), log2 domain; stage in smem.
    if (tid < SS) {
        int lab = (tid & 1) ? __ldg(&targets[b*LL + (tid >> 1)]) : 0;
        float lp2 = (rowp[lab] - sLogZ) * LOG2E;
        slp[tid] = lp2;
        bool csf = false;
        if (tid & 1) {
            int pl = (tid >= 3) ? __ldg(&targets[b*LL + ((tid - 2) >> 1)]) : -1;
            csf = (lab != 0) && (lab != pl);
        }
        scs[tid] = csf ? 1 : 0;
        // scan only reads even rows + row 511 directly
        if (((t & 1) == 0) || t == TT-1)
            g_lp[(size_t)row * SS + tid] = lp2;
    }
    __syncthreads();

    // 2-step weights for odd t (pair p = (t-1)/2, covering t, t+1)
    if ((t & 1) && t <= TT-3 && tid < SS) {
        int sidx = tid;
        float L0 = slp[sidx];
        float L1 = (sidx >= 1) ? slp[sidx-1] : NEGF;
        float L2 = (sidx >= 2) ? slp[sidx-2] : NEGF;
        bool c0 = scs[sidx];
        bool c1 = (sidx >= 1) ? (scs[sidx-1] != 0) : false;
        bool c2 = (sidx >= 2) ? (scs[sidx-2] != 0) : false;
        float w0 = L0;
        float w1 = lse2w(L0, L1);
        float w2 = lse3w(c0 ? L0 : NEGF, L1, c0 ? L2 : NEGF);
        float w3 = lse2w(c1 ? L1 : NEGF, c0 ? L2 : NEGF);
        float w4 = (c0 && c2) ? L2 : NEGF;
        int pr = (t - 1) >> 1;
        size_t base = ((size_t)(pr*BB + b) * 5) * SS + sidx;
        g_w[base + 0*SS] = w0;
        g_w[base + 1*SS] = w1;
        g_w[base + 2*SS] = w2;
        g_w[base + 3*SS] = w3;
        g_w[base + 4*SS] = w4;
    }
}

// ---------------------------------------------------------------------------
// K2: alpha scan via composed 2-step operator, DEEP software pipeline:
//     2 groups (8 t-steps, 24 loads/thread) in flight -> DRAM latency hidden.
// ---------------------------------------------------------------------------

// load group g into register buffer W[10] + L0,L1 (all indices compile-time)
#define LOADGRP(g, W, L0, L1) do {                                             \
    int _g = (g);                                                              \
    bool _ok = live && (_g < NGRP);                                            \
    _Pragma("unroll")                                                          \
    for (int _i = 0; _i < 5; _i++) {                                           \
        (W)[_i]   = _ok ? g_w[((size_t)((2*_g)*BB + b)*5 + _i)*SS + s]   : NEGF; \
        (W)[5+_i] = _ok ? g_w[((size_t)((2*_g+1)*BB + b)*5 + _i)*SS + s] : NEGF; \
    }                                                                          \
    (L0) = _ok ? g_lp[(size_t)((4*_g+2)*BB + b)*SS + s] : 0.f;                 \
    (L1) = _ok ? g_lp[(size_t)((4*_g+4)*BB + b)*SS + s] : 0.f;                 \
} while (0)

#define PROCGRP(W, L0, L1, PP) do {                                            \
    a = pairstep(a, (W)[0], (W)[1], (W)[2], (W)[3], (W)[4], (L0));             \
    a = pairstep(a, (W)[5], (W)[6], (W)[7], (W)[8], (W)[9], (L1));             \
    if (l >= 32 - MIR) bnd[PP][w*MIR + (l - (32 - MIR))] = a;                  \
    __syncthreads();                                                           \
    if (l < MIR) a = (w > 0) ? bnd[PP][(w - 1)*MIR + l] : NEGF;                \
} while (0)

__global__ __launch_bounds__(32*SWARPS) void scan_kernel(const int* __restrict__ targets,
                                                         const int* __restrict__ act_lens,
                                                         const int* __restrict__ label_lens,
                                                         float* __restrict__ out) {
    const int b   = blockIdx.x;
    const int tid = threadIdx.x;
    const int w   = tid >> 5;
    const int l   = tid & 31;
    const int s   = OWN * w + l - MIR;         // state id (mirrors for l<8)
    const bool live = (s >= 0 && s < SS);
    const bool owned = (l >= MIR) && live;
    const int alen = act_lens[b];

    __shared__ float bnd[2][SWARPS*MIR];
    __shared__ float fin[SS];

    bool cs = false;                           // can_skip (odd states only)
    if (live && (s & 1)) {
        int cl = targets[b*LL + (s >> 1)];
        int pl = (s >= 3) ? targets[b*LL + ((s - 2) >> 1)] : -1;
        cs = (cl != 0) && (cl != pl);
    }

    // composed 2-step operator
    auto pairstep = [&](float av, float w0, float w1, float w2, float w3,
                        float w4, float lpn) -> float {
        float x0 = av + w0;
        float x1 = __shfl_up_sync(0xffffffffu, av, 1) + w1;
        float x2 = __shfl_up_sync(0xffffffffu, av, 2) + w2;
        float x3 = __shfl_up_sync(0xffffffffu, av, 3) + w3;
        float x4 = __shfl_up_sync(0xffffffffu, av, 4) + w4;
        float mm = fmaxf(fmaxf(fmaxf(x0, x1), fmaxf(x2, x3)), x4);
        float r = ex2f(x0 - mm) + ex2f(x1 - mm) + ex2f(x2 - mm)
                + ex2f(x3 - mm) + ex2f(x4 - mm);
        float nv = mm + lg2f(r) + lpn;
        return live ? nv : NEGF;
    };
    // classic single step (lse3)
    auto step1 = [&](float av, float lp, int t) -> float {
        float x2 = __shfl_up_sync(0xffffffffu, av, 1);
        float x3 = __shfl_up_sync(0xffffffffu, av, 2);
        float x3e = cs ? x3 : NEGF;
        float mm = fmaxf(av, fmaxf(x2, x3e));
        float r = ex2f(av - mm) + ex2f(x2 - mm) + ex2f(x3e - mm);
        float nv = mm + lg2f(r) + lp;
        nv = (t < alen) ? nv : av;
        return live ? nv : NEGF;
    };

    // alpha[0]
    float a = NEGF;
    if (live && s <= 1) a = g_lp[(size_t)b * SS + s];

    if (alen >= TT) {
        // ---------------- fast path: no freezing anywhere ----------------
        // tail prefetch: leftover pair p=254 (t=509,510) + final step t=511
        float wT0, wT1, wT2, wT3, wT4, lnT, lnTail;
        {
            size_t base = ((size_t)(254*BB + b) * 5) * SS + (live ? s : 0);
            wT0 = live ? g_w[base + 0*SS] : NEGF;
            wT1 = live ? g_w[base + 1*SS] : NEGF;
            wT2 = live ? g_w[base + 2*SS] : NEGF;
            wT3 = live ? g_w[base + 3*SS] : NEGF;
            wT4 = live ? g_w[base + 4*SS] : NEGF;
            lnT    = live ? g_lp[(size_t)(510*BB + b)*SS + s] : 0.f;
            lnTail = live ? g_lp[(size_t)(511*BB + b)*SS + s] : 0.f;
        }

        // 2-group software pipeline: P0/P1 active, T0/T1 prefetch (distance 2)
        float P0w[10], P1w[10], T0w[10], T1w[10];
        float P0l0, P0l1, P1l0, P1l1, T0l0, T0l1, T1l0, T1l1;

        LOADGRP(0, P0w, P0l0, P0l1);
        LOADGRP(1, P1w, P1l0, P1l1);
        __syncthreads();

        for (int g0 = 0; g0 < NGRP - 1; g0 += 2) {      // g0 = 0..124, 126 groups
            LOADGRP(g0 + 2, T0w, T0l0, T0l1);
            LOADGRP(g0 + 3, T1w, T1l0, T1l1);

            PROCGRP(P0w, P0l0, P0l1, 0);
            PROCGRP(P1w, P1l0, P1l1, 1);

            #pragma unroll
            for (int i = 0; i < 10; i++) { P0w[i] = T0w[i]; P1w[i] = T1w[i]; }
            P0l0 = T0l0; P0l1 = T0l1; P1l0 = T1l0; P1l1 = T1l1;
        }
        // last group (126) is in P0
        PROCGRP(P0w, P0l0, P0l1, 0);

        // leftover pair p=254 (t=509,510): consumes mirror lanes 0..3
        a = pairstep(a, wT0, wT1, wT2, wT3, wT4, lnT);
        // final step t=511: consumes 2 more mirror lanes
        a = step1(a, lnTail, 511);
    } else {
        // ---------------- fallback: generic per-step smem scan ----------------
        __shared__ float sal[2][SS];
        if (live) sal[0][s] = a;
        __syncthreads();
        int cur = 1;
        for (int t = 1; t < TT; t++) {
            if (live) {
                float a1 = sal[cur^1][s];
                float a2 = (s >= 1) ? sal[cur^1][s-1] : NEGF;
                float a3 = (cs && s >= 2) ? sal[cur^1][s-2] : NEGF;
                float mm = fmaxf(a1, fmaxf(a2, a3));
                float r = ex2f(a1 - mm) + ex2f(a2 - mm) + ex2f(a3 - mm);
                float lp = ((t & 1) == 0 || t == TT-1)
                         ? g_lp[(size_t)(t*BB + b)*SS + s]
                         : (t < TT-2 ? (g_w[((size_t)(((t-1)>>1)*BB + b)*5 + 0)*SS + s]) : 0.f);
                float nv = mm + lg2f(r) + lp;   // w0 == lp for odd t rows
                sal[cur][s] = (t < alen) ? nv : a1;
            }
            __syncthreads();
            cur ^= 1;
        }
        a = live ? sal[cur^1][s] : NEGF;
    }

    if (owned) fin[s] = a;
    __syncthreads();
    if (tid == 0) {
        int sl = 2 * label_lens[b];
        float x = fin[sl], y = fin[sl - 1];
        float m = fmaxf(x, y);
        float ll2 = m + lg2f(ex2f(x - m) + ex2f(y - m));   // log2 domain
        atomicAdd(out, -ll2 * (LN2 / (float)BB));
    }
}

// ---------------------------------------------------------------------------
extern "C" void kernel_launch(void* const* d_in, const int* in_sizes, int n_in,
                              void* d_out, int out_size) {
    const float* acts       = (const float*)d_in[0];
    const int*   targets    = (const int*)d_in[1];
    const int*   act_lens   = (const int*)d_in[2];
    const int*   label_lens = (const int*)d_in[3];
    float* out = (float*)d_out;

    logz_gather_kernel<<<TT*BB, 256>>>(acts, targets, out);
    scan_kernel<<<BB, 32*SWARPS>>>(targets, act_lens, label_lens, out);
}

// round 12
// speedup vs baseline: 1.2525x; 1.0625x over previous
#include <cuda_runtime.h>
#include <cuda_bf16.h>

#define TT 512
#define BB 32
#define VV 8000
#define LL 100
#define SS (2*LL+1)   // 201
#define NEGF (-1e30f)
#define LOG2E 1.4426950408889634f
#define LN2   0.6931471805599453f

#define SWARPS 9      // scan warps per sample
#define OWN   24      // owned states per warp (lanes 8..31)
#define MIR    8      // mirror lanes (0..7) = prev warp's top 8 states
#define NPAIRS 255    // 2-step pairs: pair p covers t = 2p+1, 2p+2 (t up to 510)
#define NGRP  127     // groups of 2 pairs (4 t-steps); leftover pair 254 + step 511

// Scratch (allocation-free rule: __device__ globals)
__device__ float g_lp[TT*BB*SS];            // log2-domain emissions, ALL rows (27 MB)
__device__ float g_sc[NPAIRS*BB*6*SS];      // packed scan input: w0..w4 + lp_next (39 MB)

__device__ __forceinline__ float ex2f(float x) {
    float r; asm("ex2.approx.ftz.f32 %0, %1;" : "=f"(r) : "f"(x)); return r;
}
__device__ __forceinline__ float lg2f(float x) {
    float r; asm("lg2.approx.ftz.f32 %0, %1;" : "=f"(r) : "f"(x)); return r;
}
__device__ __forceinline__ float lse2w(float x, float y) {       // log2 domain
    float m = fmaxf(x, y);
    return m + lg2f(ex2f(x - m) + ex2f(y - m));
}
__device__ __forceinline__ float lse3w(float x, float y, float z) {
    float m = fmaxf(x, fmaxf(y, z));
    return m + lg2f(ex2f(x - m) + ex2f(y - m) + ex2f(z - m));
}

// ---------------------------------------------------------------------------
// K1a: logZ over V + gather lp_ext (log2 domain) for ALL rows.
// ---------------------------------------------------------------------------
__global__ __launch_bounds__(256) void logz_gather_kernel(const float* __restrict__ acts,
                                                          const int* __restrict__ targets,
                                                          float* __restrict__ out) {
    const int row = blockIdx.x;                    // t*BB + b
    const int b   = row % BB;
    const float* __restrict__ rowp = acts + (size_t)row * VV;
    const float4* __restrict__ p = (const float4*)rowp;
    const int tid = threadIdx.x;

    if (row == 0 && tid == 0) out[0] = 0.f;        // zero the batch-mean accumulator

    float m = NEGF, s = 0.f;
    #pragma unroll 4
    for (int i = tid; i < VV/4; i += 256) {
        float4 v = p[i];
        float mx = fmaxf(fmaxf(v.x, v.y), fmaxf(v.z, v.w));
        if (mx > m) { s *= __expf(m - mx); m = mx; }
        s += __expf(v.x - m) + __expf(v.y - m) + __expf(v.z - m) + __expf(v.w - m);
    }
    #pragma unroll
    for (int off = 16; off; off >>= 1) {
        float m2 = __shfl_xor_sync(0xffffffffu, m, off);
        float s2 = __shfl_xor_sync(0xffffffffu, s, off);
        float M = fmaxf(m, m2);
        s = s * __expf(m - M) + s2 * __expf(m2 - M);
        m = M;
    }
    __shared__ float sm[8], sv[8];
    __shared__ float sLogZ;
    int w = tid >> 5;
    if ((tid & 31) == 0) { sm[w] = m; sv[w] = s; }
    __syncthreads();
    if (tid == 0) {
        float M = sm[0], Sv = sv[0];
        #pragma unroll
        for (int i = 1; i < 8; i++) {
            float m2 = sm[i], s2 = sv[i];
            float Mn = fmaxf(M, m2);
            Sv = Sv * __expf(M - Mn) + s2 * __expf(m2 - Mn);
            M = Mn;
        }
        sLogZ = M + __logf(Sv);
    }
    __syncthreads();

    // Gather 201 extended-label emissions (L1 hits), log2 domain.
    if (tid < SS) {
        int lab = (tid & 1) ? __ldg(&targets[b*LL + (tid >> 1)]) : 0;
        g_lp[(size_t)row * SS + tid] = (rowp[lab] - sLogZ) * LOG2E;
    }
}

// ---------------------------------------------------------------------------
// K1b: 2-step composed weights, packed with lp_next into g_sc.
//      Runs AFTER the big stream -> its 39 MB output stays L2-resident for
//      the scan. One block per (pair, b).
// ---------------------------------------------------------------------------
__global__ __launch_bounds__(256) void weights_kernel(const int* __restrict__ targets) {
    const int pr = blockIdx.x / BB;            // pair 0..254, t = 2*pr+1
    const int b  = blockIdx.x % BB;
    const int t  = 2*pr + 1;
    const int tid = threadIdx.x;

    __shared__ float slp[SS];
    __shared__ unsigned char scs[SS];

    if (tid < SS) {
        slp[tid] = g_lp[(size_t)(t*BB + b)*SS + tid];
        bool csf = false;
        if (tid & 1) {
            int lab = __ldg(&targets[b*LL + (tid >> 1)]);
            int pl  = (tid >= 3) ? __ldg(&targets[b*LL + ((tid - 2) >> 1)]) : -1;
            csf = (lab != 0) && (lab != pl);
        }
        scs[tid] = csf ? 1 : 0;
    }
    __syncthreads();

    if (tid < SS) {
        float L0 = slp[tid];
        float L1 = (tid >= 1) ? slp[tid-1] : NEGF;
        float L2 = (tid >= 2) ? slp[tid-2] : NEGF;
        bool c0 = scs[tid];
        bool c1 = (tid >= 1) ? (scs[tid-1] != 0) : false;
        bool c2 = (tid >= 2) ? (scs[tid-2] != 0) : false;
        float w0 = L0;
        float w1 = lse2w(L0, L1);
        float w2 = lse3w(c0 ? L0 : NEGF, L1, c0 ? L2 : NEGF);
        float w3 = lse2w(c1 ? L1 : NEGF, c0 ? L2 : NEGF);
        float w4 = (c0 && c2) ? L2 : NEGF;
        float lpn = g_lp[(size_t)((t+1)*BB + b)*SS + tid];
        size_t base = ((size_t)(pr*BB + b) * 6) * SS + tid;
        g_sc[base + 0*SS] = w0;
        g_sc[base + 1*SS] = w1;
        g_sc[base + 2*SS] = w2;
        g_sc[base + 3*SS] = w3;
        g_sc[base + 4*SS] = w4;
        g_sc[base + 5*SS] = lpn;
    }
}

// ---------------------------------------------------------------------------
// K2: composed 2-step scan, deep pipeline, input L2-resident in g_sc.
// ---------------------------------------------------------------------------

// load group g (pairs 2g, 2g+1): 12 floats, compile-time slot indices
#define LOADGRP(g, W) do {                                                     \
    int _g = (g);                                                              \
    bool _ok = live && (_g < NGRP);                                            \
    _Pragma("unroll")                                                          \
    for (int _i = 0; _i < 6; _i++) {                                           \
        (W)[_i]   = _ok ? g_sc[((size_t)((2*_g)*BB + b)*6 + _i)*SS + s]   : ((_i==5)?0.f:NEGF); \
        (W)[6+_i] = _ok ? g_sc[((size_t)((2*_g+1)*BB + b)*6 + _i)*SS + s] : ((_i==5)?0.f:NEGF); \
    }                                                                          \
} while (0)

#define PROCGRP(W, PP) do {                                                    \
    a = pairstep(a, (W)[0], (W)[1], (W)[2], (W)[3], (W)[4], (W)[5]);           \
    a = pairstep(a, (W)[6], (W)[7], (W)[8], (W)[9], (W)[10], (W)[11]);         \
    if (l >= 32 - MIR) bnd[PP][w*MIR + (l - (32 - MIR))] = a;                  \
    __syncthreads();                                                           \
    if (l < MIR) a = (w > 0) ? bnd[PP][(w - 1)*MIR + l] : NEGF;                \
} while (0)

__global__ __launch_bounds__(32*SWARPS) void scan_kernel(const int* __restrict__ targets,
                                                         const int* __restrict__ act_lens,
                                                         const int* __restrict__ label_lens,
                                                         float* __restrict__ out) {
    const int b   = blockIdx.x;
    const int tid = threadIdx.x;
    const int w   = tid >> 5;
    const int l   = tid & 31;
    const int s   = OWN * w + l - MIR;         // state id (mirrors for l<8)
    const bool live = (s >= 0 && s < SS);
    const bool owned = (l >= MIR) && live;
    const int alen = act_lens[b];

    __shared__ float bnd[2][SWARPS*MIR];
    __shared__ float fin[SS];

    bool cs = false;                           // can_skip (odd states only)
    if (live && (s & 1)) {
        int cl = targets[b*LL + (s >> 1)];
        int pl = (s >= 3) ? targets[b*LL + ((s - 2) >> 1)] : -1;
        cs = (cl != 0) && (cl != pl);
    }

    auto pairstep = [&](float av, float w0, float w1, float w2, float w3,
                        float w4, float lpn) -> float {
        float x0 = av + w0;
        float x1 = __shfl_up_sync(0xffffffffu, av, 1) + w1;
        float x2 = __shfl_up_sync(0xffffffffu, av, 2) + w2;
        float x3 = __shfl_up_sync(0xffffffffu, av, 3) + w3;
        float x4 = __shfl_up_sync(0xffffffffu, av, 4) + w4;
        float mm = fmaxf(fmaxf(fmaxf(x0, x1), fmaxf(x2, x3)), x4);
        float r = ex2f(x0 - mm) + ex2f(x1 - mm) + ex2f(x2 - mm)
                + ex2f(x3 - mm) + ex2f(x4 - mm);
        float nv = mm + lg2f(r) + lpn;
        return live ? nv : NEGF;
    };
    auto step1 = [&](float av, float lp, int t) -> float {
        float x2 = __shfl_up_sync(0xffffffffu, av, 1);
        float x3 = __shfl_up_sync(0xffffffffu, av, 2);
        float x3e = cs ? x3 : NEGF;
        float mm = fmaxf(av, fmaxf(x2, x3e));
        float r = ex2f(av - mm) + ex2f(x2 - mm) + ex2f(x3e - mm);
        float nv = mm + lg2f(r) + lp;
        nv = (t < alen) ? nv : av;
        return live ? nv : NEGF;
    };

    // alpha[0]
    float a = NEGF;
    if (live && s <= 1) a = g_lp[(size_t)b * SS + s];

    if (alen >= TT) {
        // tail prefetch: leftover pair p=254 (t=509,510) + final step t=511
        float wt[6], lnTail;
        {
            size_t base = ((size_t)(254*BB + b) * 6) * SS + (live ? s : 0);
            #pragma unroll
            for (int i = 0; i < 6; i++) wt[i] = live ? g_sc[base + (size_t)i*SS] : ((i==5)?0.f:NEGF);
            lnTail = live ? g_lp[(size_t)(511*BB + b)*SS + s] : 0.f;
        }

        // 2-group software pipeline (distance 2)
        float P0[12], P1[12], T0[12], T1[12];
        LOADGRP(0, P0);
        LOADGRP(1, P1);
        __syncthreads();

        for (int g0 = 0; g0 < NGRP - 1; g0 += 2) {      // 126 groups in the loop
            LOADGRP(g0 + 2, T0);
            LOADGRP(g0 + 3, T1);

            PROCGRP(P0, 0);
            PROCGRP(P1, 1);

            #pragma unroll
            for (int i = 0; i < 12; i++) { P0[i] = T0[i]; P1[i] = T1[i]; }
        }
        // last group (126) in P0
        PROCGRP(P0, 0);

        // leftover pair p=254 (t=509,510): consumes mirror lanes 0..3
        a = pairstep(a, wt[0], wt[1], wt[2], wt[3], wt[4], wt[5]);
        // final step t=511: consumes 2 more mirror lanes
        a = step1(a, lnTail, 511);
    } else {
        // fallback: generic per-step smem scan over full g_lp
        __shared__ float sal[2][SS];
        if (live) sal[0][s] = a;
        __syncthreads();
        int cur = 1;
        for (int t = 1; t < TT; t++) {
            if (live) {
                float a1 = sal[cur^1][s];
                float a2 = (s >= 1) ? sal[cur^1][s-1] : NEGF;
                float a3 = (cs && s >= 2) ? sal[cur^1][s-2] : NEGF;
                float mm = fmaxf(a1, fmaxf(a2, a3));
                float r = ex2f(a1 - mm) + ex2f(a2 - mm) + ex2f(a3 - mm);
                float lp = g_lp[(size_t)(t*BB + b)*SS + s];
                float nv = mm + lg2f(r) + lp;
                sal[cur][s] = (t < alen) ? nv : a1;
            }
            __syncthreads();
            cur ^= 1;
        }
        a = live ? sal[cur^1][s] : NEGF;
    }

    if (owned) fin[s] = a;
    __syncthreads();
    if (tid == 0) {
        int sl = 2 * label_lens[b];
        float x = fin[sl], y = fin[sl - 1];
        float m = fmaxf(x, y);
        float ll2 = m + lg2f(ex2f(x - m) + ex2f(y - m));   // log2 domain
        atomicAdd(out, -ll2 * (LN2 / (float)BB));
    }
}

// ---------------------------------------------------------------------------
extern "C" void kernel_launch(void* const* d_in, const int* in_sizes, int n_in,
                              void* d_out, int out_size) {
    const float* acts       = (const float*)d_in[0];
    const int*   targets    = (const int*)d_in[1];
    const int*   act_lens   = (const int*)d_in[2];
    const int*   label_lens = (const int*)d_in[3];
    float* out = (float*)d_out;

    logz_gather_kernel<<<TT*BB, 256>>>(acts, targets, out);
    weights_kernel<<<NPAIRS*BB, 256>>>(targets);
    scan_kernel<<<BB, 32*SWARPS>>>(targets, act_lens, label_lens, out);
}